// round 4
// baseline (speedup 1.0000x reference)
#include <cuda_runtime.h>
#include <cuda_fp16.h>
#include <math.h>

#define NN 20000
#define EE 80000
#define GG 1000
#define FTOT 16
#define CSD 5
#define FCIN 75

// ---------------- device scratch (allocation-free contract) ----------------
__device__ float g_hA[NN * 64];
__device__ float g_hB[NN * 64];
__device__ float g_hid[(size_t)EE * 128];
__device__ __half g_Ph[(size_t)NN * 128 * 64];   // packed: (n,k,o) -> n*COLS + (k>>1)*2*MO + 2*o + (k&1)
__device__ float g_R[NN * 64];
__device__ float g_agg[NN * 64];
__device__ float g_gsum[GG * FCIN];
__device__ float g_gcnt[GG];

__device__ __forceinline__ float* hbuf(int s) { return s ? g_hB : g_hA; }
__device__ __forceinline__ float elu_f(float x) { return x > 0.f ? x : (expf(x) - 1.f); }

// ---- packed fp32x2 helpers (sm_100+ PTX; ptxas won't auto-emit FFMA2) ----
__device__ __forceinline__ unsigned long long pack2(float x, float y) {
    unsigned long long r;
    asm("mov.b64 %0, {%1, %2};" : "=l"(r) : "f"(x), "f"(y));
    return r;
}
__device__ __forceinline__ unsigned long long ffma2(unsigned long long a, unsigned long long b,
                                                    unsigned long long c) {
    unsigned long long d;
    asm("fma.rn.f32x2 %0, %1, %2, %3;" : "=l"(d) : "l"(a), "l"(b), "l"(c));
    return d;
}
__device__ __forceinline__ float2 unpack2(unsigned long long a) {
    float2 f;
    asm("mov.b64 {%0, %1}, %2;" : "=f"(f.x), "=f"(f.y) : "l"(a));
    return f;
}

// ---------------- kernels ----------------

__global__ void init_h0_kernel(const float* __restrict__ x) {
    int idx = blockIdx.x * blockDim.x + threadIdx.x;
    if (idx >= NN * CSD) return;
    int n = idx / CSD, i = idx % CSD;
    g_hA[n * CSD + i] = x[n * FTOT + i];
}

// hid[e,k] = relu(b1[k] + sum_a ea[e,a]*w1[a,k])
__global__ void hid_kernel(const float* __restrict__ ea,
                           const float* __restrict__ w1,
                           const float* __restrict__ b1) {
    int e = blockIdx.x;
    int k = threadIdx.x;
    __shared__ float a[5];
    if (k < 5) a[k] = ea[e * 5 + k];
    __syncthreads();
    float s = b1[k];
#pragma unroll
    for (int i = 0; i < 5; i++) s = fmaf(a[i], w1[i * 128 + k], s);
    g_hid[(size_t)e * 128 + k] = fmaxf(s, 0.f);
}

// P[n,(k,o)] = sum_i h[n,i]*w2[k,i,o]  -> fp16, packed half2 over (k,k+1) at fixed o.
// GEMM tile: 64 nodes x 128 packed cols, 256 threads, microtile 4 nodes x 8 cols via FFMA2.
template <int MI, int MO>
__global__ __launch_bounds__(256) void p2_kernel(const float* __restrict__ w2, int insel) {
    const int COLS = 128 * MO;
    __shared__ float As[MI][64];   // [i][n]
    __shared__ float Bs[MI][128];  // [i][local q]
    const float* h = hbuf(insel);
    int nb = blockIdx.y * 64;
    int qb = blockIdx.x * 128;
    int t = threadIdx.x;

    for (int idx = t; idx < 64 * MI; idx += 256) {
        int n = idx / MI, i = idx % MI;
        As[i][n] = (nb + n < NN) ? h[(nb + n) * MI + i] : 0.f;
    }
    for (int idx = t; idx < MI * 128; idx += 256) {
        int i = idx >> 7, ql = idx & 127;
        int q = qb + ql;
        int kk = q / (2 * MO);
        int rem = q % (2 * MO);
        int o = rem >> 1;
        int k = 2 * kk + (rem & 1);
        Bs[i][ql] = w2[(k * MI + i) * MO + o];
    }
    __syncthreads();

    int cr = (t & 15) * 8;   // 8 packed cols
    int nr = (t >> 4) * 4;   // 4 nodes

    unsigned long long acc[4][4];
#pragma unroll
    for (int n = 0; n < 4; n++)
#pragma unroll
        for (int j = 0; j < 4; j++) acc[n][j] = 0ull;

#pragma unroll
    for (int i = 0; i < MI; i++) {
        float4 a4 = *(const float4*)&As[i][nr];
        unsigned long long ap[4];
        ap[0] = pack2(a4.x, a4.x);
        ap[1] = pack2(a4.y, a4.y);
        ap[2] = pack2(a4.z, a4.z);
        ap[3] = pack2(a4.w, a4.w);
        const unsigned long long* bp = (const unsigned long long*)&Bs[i][cr];
        unsigned long long b0 = bp[0], b1 = bp[1], b2 = bp[2], b3 = bp[3];
#pragma unroll
        for (int n = 0; n < 4; n++) {
            acc[n][0] = ffma2(ap[n], b0, acc[n][0]);
            acc[n][1] = ffma2(ap[n], b1, acc[n][1]);
            acc[n][2] = ffma2(ap[n], b2, acc[n][2]);
            acc[n][3] = ffma2(ap[n], b3, acc[n][3]);
        }
    }

#pragma unroll
    for (int n = 0; n < 4; n++) {
        int node = nb + nr + n;
        if (node < NN) {
            uint4 out;
            unsigned* op = (unsigned*)&out;
#pragma unroll
            for (int j = 0; j < 4; j++) {
                float2 f = unpack2(acc[n][j]);
                __half2 h2 = __float22half2_rn(f);
                op[j] = *(unsigned*)&h2;
            }
            *(uint4*)&g_Ph[(size_t)node * COLS + qb + cr] = out;
        }
    }
}

// R[n,o] = h[n]@b2[:,o] ; agg[n,o] = bias[o] + h[n]@root[:,o]   (agg pre-seeded with root term)
template <int MI, int MO>
__global__ void rb_kernel(const float* __restrict__ b2,
                          const float* __restrict__ root,
                          const float* __restrict__ bias, int insel) {
    int idx = blockIdx.x * blockDim.x + threadIdx.x;
    if (idx >= NN * MO) return;
    int n = idx / MO, o = idx % MO;
    const float* h = hbuf(insel);
    float sr = 0.f, sa = bias[o];
#pragma unroll
    for (int i = 0; i < MI; i++) {
        float hv = h[n * MI + i];
        sr = fmaf(hv, b2[i * MO + o], sr);
        sa = fmaf(hv, root[i * MO + o], sa);
    }
    g_R[n * MO + o] = sr;
    g_agg[n * MO + o] = sa;
}

// msg[e,o] = R[src,o] + sum_k hid[e,k]*P[src,k,o]; atomic scatter to agg[dst]
template <int MO>
__global__ __launch_bounds__(256) void edge2_kernel(const int* __restrict__ ei) {
    const int EPB = 256 / MO;
    const int COLS = 128 * MO;
    __shared__ float hs[EPB][128];
    __shared__ int ssrc[EPB], sdst[EPB];
    int t = threadIdx.x;
    int e0 = blockIdx.x * EPB;
    {
        const float4* hv = (const float4*)&g_hid[(size_t)e0 * 128];
        float4* hsv = (float4*)hs;
        for (int idx = t; idx < EPB * 32; idx += 256) hsv[idx] = hv[idx];
    }
    if (t < EPB) {
        ssrc[t] = ei[e0 + t];
        sdst[t] = ei[EE + e0 + t];
    }
    __syncthreads();
    int le = t / MO, o = t % MO;
    int src = ssrc[le], dst = sdst[le];
    const __half2* Pp = (const __half2*)&g_Ph[(size_t)src * COLS + 2 * o];
    const float2* hvv = (const float2*)hs[le];
    float acc = g_R[src * MO + o];
    float acc2 = 0.f;
#pragma unroll 16
    for (int kk = 0; kk < 64; kk++) {
        float2 p = __half22float2(Pp[(size_t)kk * MO]);
        float2 hh = hvv[kk];
        acc = fmaf(hh.x, p.x, acc);
        acc2 = fmaf(hh.y, p.y, acc2);
    }
    atomicAdd(&g_agg[dst * MO + o], acc + acc2);
}

// h_out = elu(agg)
template <int MO>
__global__ void elu_kernel(int outsel) {
    int idx = blockIdx.x * blockDim.x + threadIdx.x;
    if (idx >= NN * MO) return;
    hbuf(outsel)[idx] = elu_f(g_agg[idx]);
}

__global__ void zero_pool_kernel() {
    int idx = blockIdx.x * blockDim.x + threadIdx.x;
    if (idx < GG * FCIN) g_gsum[idx] = 0.f;
    if (idx < GG) g_gcnt[idx] = 0.f;
}

__global__ void pool_scatter_kernel(const float* __restrict__ x,
                                    const int* __restrict__ batch, int hsel) {
    int idx = blockIdx.x * blockDim.x + threadIdx.x;
    if (idx >= NN * FCIN) return;
    int n = idx / FCIN, d = idx % FCIN;
    const float* h = hbuf(hsel);
    float v = (d < 64) ? h[n * 64 + d] : x[n * FTOT + CSD + (d - 64)];
    int b = batch[n];
    atomicAdd(&g_gsum[b * FCIN + d], v);
    if (d == 0) atomicAdd(&g_gcnt[b], 1.f);
}

__global__ void mlp_kernel(const float* __restrict__ fc1w, const float* __restrict__ fc1b,
                           const float* __restrict__ fc2w, const float* __restrict__ fc2b,
                           const float* __restrict__ fc3w, const float* __restrict__ fc3b,
                           float* __restrict__ out) {
    int g = blockIdx.x;
    int t = threadIdx.x;  // 32
    __shared__ float gv[FCIN], a1[32], a2[16];
    float cnt = fmaxf(g_gcnt[g], 1.f);
    for (int i = t; i < FCIN; i += 32) gv[i] = g_gsum[g * FCIN + i] / cnt;
    __syncthreads();
    {
        float s = fc1b[t];
        for (int i = 0; i < FCIN; i++) s = fmaf(gv[i], fc1w[i * 32 + t], s);
        a1[t] = elu_f(s);
    }
    __syncthreads();
    if (t < 16) {
        float s = fc2b[t];
#pragma unroll
        for (int i = 0; i < 32; i++) s = fmaf(a1[i], fc2w[i * 16 + t], s);
        a2[t] = elu_f(s);
    }
    __syncthreads();
    if (t == 0) {
        float s = fc3b[0];
#pragma unroll
        for (int i = 0; i < 16; i++) s = fmaf(a2[i], fc3w[i], s);
        out[g] = s;
    }
}

// ---------------- host side ----------------

template <int MI, int MO>
static void run_layer(const float* ea, const int* ei,
                      const float* w1, const float* b1,
                      const float* w2, const float* b2,
                      const float* root, const float* bias,
                      int insel, int outsel) {
    hid_kernel<<<EE, 128>>>(ea, w1, b1);
    dim3 pg(MO, (NN + 63) / 64);
    p2_kernel<MI, MO><<<pg, 256>>>(w2, insel);
    rb_kernel<MI, MO><<<(NN * MO + 255) / 256, 256>>>(b2, root, bias, insel);
    edge2_kernel<MO><<<EE / (256 / MO), 256>>>(ei);
    elu_kernel<MO><<<(NN * MO + 255) / 256, 256>>>(outsel);
}

extern "C" void kernel_launch(void* const* d_in, const int* in_sizes, int n_in,
                              void* d_out, int out_size) {
    const float* x  = (const float*)d_in[0];
    const int*   ei = (const int*)d_in[1];
    const float* ea = (const float*)d_in[2];
    const int*   batch = (const int*)d_in[3];

    const float* c1w1 = (const float*)d_in[4];
    const float* c1b1 = (const float*)d_in[5];
    const float* c1w2 = (const float*)d_in[6];
    const float* c1b2 = (const float*)d_in[7];
    const float* c1root = (const float*)d_in[8];
    const float* c1bias = (const float*)d_in[9];

    const float* c2w1 = (const float*)d_in[10];
    const float* c2b1 = (const float*)d_in[11];
    const float* c2w2 = (const float*)d_in[12];
    const float* c2b2 = (const float*)d_in[13];
    const float* c2root = (const float*)d_in[14];
    const float* c2bias = (const float*)d_in[15];

    const float* c3w1 = (const float*)d_in[16];
    const float* c3b1 = (const float*)d_in[17];
    const float* c3w2 = (const float*)d_in[18];
    const float* c3b2 = (const float*)d_in[19];
    const float* c3root = (const float*)d_in[20];
    const float* c3bias = (const float*)d_in[21];

    const float* fc1w = (const float*)d_in[22];
    const float* fc1b = (const float*)d_in[23];
    const float* fc2w = (const float*)d_in[24];
    const float* fc2b = (const float*)d_in[25];
    const float* fc3w = (const float*)d_in[26];
    const float* fc3b = (const float*)d_in[27];

    init_h0_kernel<<<(NN * CSD + 255) / 256, 256>>>(x);

    run_layer<5, 32>(ea, ei, c1w1, c1b1, c1w2, c1b2, c1root, c1bias, 0, 1);
    run_layer<32, 64>(ea, ei, c2w1, c2b1, c2w2, c2b2, c2root, c2bias, 1, 0);
    run_layer<64, 64>(ea, ei, c3w1, c3b1, c3w2, c3b2, c3root, c3bias, 0, 1);

    zero_pool_kernel<<<(GG * FCIN + 255) / 256, 256>>>();
    pool_scatter_kernel<<<(NN * FCIN + 255) / 256, 256>>>(x, batch, 1);
    mlp_kernel<<<GG, 32>>>(fc1w, fc1b, fc2w, fc2b, fc3w, fc3b, (float*)d_out);
}

// round 9
// speedup vs baseline: 1.4665x; 1.4665x over previous
#include <cuda_runtime.h>
#include <cuda_fp16.h>
#include <math.h>

#define NN 20000
#define EE 80000
#define GG 1000
#define FTOT 16
#define CSD 5
#define FCIN 75

// ---------------- device scratch (allocation-free contract) ----------------
__device__ float g_hA[NN * 64];
__device__ float g_hB[NN * 64];
__device__ float g_hid[(size_t)EE * 128];
__device__ __half g_Ph[(size_t)NN * 128 * 64];   // packed: (n,k,o) -> n*COLS + (k>>1)*2*MO + 2*o + (k&1)
__device__ float g_R[NN * 64];
__device__ float g_agg[NN * 64];
__device__ float g_gsum[GG * FCIN];
__device__ float g_gcnt[GG];

__device__ __forceinline__ float* hbuf(int s) { return s ? g_hB : g_hA; }
__device__ __forceinline__ float elu_f(float x) { return x > 0.f ? x : (expf(x) - 1.f); }

// ---------------- kernels ----------------

__global__ void init_h0_kernel(const float* __restrict__ x) {
    int idx = blockIdx.x * blockDim.x + threadIdx.x;
    if (idx >= NN * CSD) return;
    int n = idx / CSD, i = idx % CSD;
    g_hA[n * CSD + i] = x[n * FTOT + i];
}

// hid[e,k] = relu(b1[k] + sum_a ea[e,a]*w1[a,k])
__global__ void hid_kernel(const float* __restrict__ ea,
                           const float* __restrict__ w1,
                           const float* __restrict__ b1) {
    int e = blockIdx.x;
    int k = threadIdx.x;
    __shared__ float a[5];
    if (k < 5) a[k] = ea[e * 5 + k];
    __syncthreads();
    float s = b1[k];
#pragma unroll
    for (int i = 0; i < 5; i++) s = fmaf(a[i], w1[i * 128 + k], s);
    g_hid[(size_t)e * 128 + k] = fmaxf(s, 0.f);
}

// P[n,(k,o)] = sum_i h[n,i]*w2[k,i,o]  -> fp16, packed half2 over (k,k+1) at fixed o.
// GEMM tile: 64 nodes x 128 cols, 256 threads, scalar FFMA microtile 4 nodes x 8 cols.
template <int MI, int MO>
__global__ __launch_bounds__(256) void p2_kernel(const float* __restrict__ w2, int insel) {
    const int COLS = 128 * MO;
    __shared__ float As[MI][64];   // [i][n]
    __shared__ float Bs[MI][128];  // [i][local q]
    const float* h = hbuf(insel);
    int nb = blockIdx.y * 64;
    int qb = blockIdx.x * 128;
    int t = threadIdx.x;

    for (int idx = t; idx < 64 * MI; idx += 256) {
        int n = idx / MI, i = idx % MI;
        As[i][n] = (nb + n < NN) ? h[(nb + n) * MI + i] : 0.f;
    }
    for (int idx = t; idx < MI * 128; idx += 256) {
        int i = idx >> 7, ql = idx & 127;
        int q = qb + ql;
        int kk = q / (2 * MO);
        int rem = q % (2 * MO);
        int o = rem >> 1;
        int k = 2 * kk + (rem & 1);
        Bs[i][ql] = w2[(k * MI + i) * MO + o];
    }
    __syncthreads();

    int cr = (t & 15) * 8;   // 8 cols
    int nr = (t >> 4) * 4;   // 4 nodes

    float acc[4][8];
#pragma unroll
    for (int n = 0; n < 4; n++)
#pragma unroll
        for (int j = 0; j < 8; j++) acc[n][j] = 0.f;

#pragma unroll
    for (int i = 0; i < MI; i++) {
        float4 a4 = *(const float4*)&As[i][nr];
        float av[4] = {a4.x, a4.y, a4.z, a4.w};
        float4 bl = *(const float4*)&Bs[i][cr];
        float4 bh = *(const float4*)&Bs[i][cr + 4];
        float bv[8] = {bl.x, bl.y, bl.z, bl.w, bh.x, bh.y, bh.z, bh.w};
#pragma unroll
        for (int n = 0; n < 4; n++)
#pragma unroll
            for (int j = 0; j < 8; j++)
                acc[n][j] = fmaf(av[n], bv[j], acc[n][j]);
    }

#pragma unroll
    for (int n = 0; n < 4; n++) {
        int node = nb + nr + n;
        if (node < NN) {
            uint4 out;
            unsigned* op = (unsigned*)&out;
#pragma unroll
            for (int j = 0; j < 4; j++) {
                __half2 h2 = __floats2half2_rn(acc[n][2 * j], acc[n][2 * j + 1]);
                op[j] = *(unsigned*)&h2;
            }
            *(uint4*)&g_Ph[(size_t)node * COLS + qb + cr] = out;
        }
    }
}

// R[n,o] = h[n]@b2[:,o] ; agg[n,o] = bias[o] + h[n]@root[:,o]   (agg pre-seeded with root term)
template <int MI, int MO>
__global__ void rb_kernel(const float* __restrict__ b2,
                          const float* __restrict__ root,
                          const float* __restrict__ bias, int insel) {
    int idx = blockIdx.x * blockDim.x + threadIdx.x;
    if (idx >= NN * MO) return;
    int n = idx / MO, o = idx % MO;
    const float* h = hbuf(insel);
    float sr = 0.f, sa = bias[o];
#pragma unroll
    for (int i = 0; i < MI; i++) {
        float hv = h[n * MI + i];
        sr = fmaf(hv, b2[i * MO + o], sr);
        sa = fmaf(hv, root[i * MO + o], sa);
    }
    g_R[n * MO + o] = sr;
    g_agg[n * MO + o] = sa;
}

// msg[e,o] = R[src,o] + sum_k hid[e,k]*P[src,k,o]; atomic scatter to agg[dst]
template <int MO>
__global__ __launch_bounds__(256) void edge2_kernel(const int* __restrict__ ei) {
    const int EPB = 256 / MO;
    const int COLS = 128 * MO;
    __shared__ float hs[EPB][128];
    __shared__ int ssrc[EPB], sdst[EPB];
    int t = threadIdx.x;
    int e0 = blockIdx.x * EPB;
    {
        const float4* hv = (const float4*)&g_hid[(size_t)e0 * 128];
        float4* hsv = (float4*)hs;
        for (int idx = t; idx < EPB * 32; idx += 256) hsv[idx] = hv[idx];
    }
    if (t < EPB) {
        ssrc[t] = ei[e0 + t];
        sdst[t] = ei[EE + e0 + t];
    }
    __syncthreads();
    int le = t / MO, o = t % MO;
    int src = ssrc[le], dst = sdst[le];
    const __half2* Pp = (const __half2*)&g_Ph[(size_t)src * COLS + 2 * o];
    const float2* hvv = (const float2*)hs[le];
    float acc = g_R[src * MO + o];
    float acc2 = 0.f;
#pragma unroll 16
    for (int kk = 0; kk < 64; kk++) {
        float2 p = __half22float2(Pp[(size_t)kk * MO]);
        float2 hh = hvv[kk];
        acc = fmaf(hh.x, p.x, acc);
        acc2 = fmaf(hh.y, p.y, acc2);
    }
    atomicAdd(&g_agg[dst * MO + o], acc + acc2);
}

// h_out = elu(agg)
template <int MO>
__global__ void elu_kernel(int outsel) {
    int idx = blockIdx.x * blockDim.x + threadIdx.x;
    if (idx >= NN * MO) return;
    hbuf(outsel)[idx] = elu_f(g_agg[idx]);
}

__global__ void zero_pool_kernel() {
    int idx = blockIdx.x * blockDim.x + threadIdx.x;
    if (idx < GG * FCIN) g_gsum[idx] = 0.f;
    if (idx < GG) g_gcnt[idx] = 0.f;
}

__global__ void pool_scatter_kernel(const float* __restrict__ x,
                                    const int* __restrict__ batch, int hsel) {
    int idx = blockIdx.x * blockDim.x + threadIdx.x;
    if (idx >= NN * FCIN) return;
    int n = idx / FCIN, d = idx % FCIN;
    const float* h = hbuf(hsel);
    float v = (d < 64) ? h[n * 64 + d] : x[n * FTOT + CSD + (d - 64)];
    int b = batch[n];
    atomicAdd(&g_gsum[b * FCIN + d], v);
    if (d == 0) atomicAdd(&g_gcnt[b], 1.f);
}

__global__ void mlp_kernel(const float* __restrict__ fc1w, const float* __restrict__ fc1b,
                           const float* __restrict__ fc2w, const float* __restrict__ fc2b,
                           const float* __restrict__ fc3w, const float* __restrict__ fc3b,
                           float* __restrict__ out) {
    int g = blockIdx.x;
    int t = threadIdx.x;  // 32
    __shared__ float gv[FCIN], a1[32], a2[16];
    float cnt = fmaxf(g_gcnt[g], 1.f);
    for (int i = t; i < FCIN; i += 32) gv[i] = g_gsum[g * FCIN + i] / cnt;
    __syncthreads();
    {
        float s = fc1b[t];
        for (int i = 0; i < FCIN; i++) s = fmaf(gv[i], fc1w[i * 32 + t], s);
        a1[t] = elu_f(s);
    }
    __syncthreads();
    if (t < 16) {
        float s = fc2b[t];
#pragma unroll
        for (int i = 0; i < 32; i++) s = fmaf(a1[i], fc2w[i * 16 + t], s);
        a2[t] = elu_f(s);
    }
    __syncthreads();
    if (t == 0) {
        float s = fc3b[0];
#pragma unroll
        for (int i = 0; i < 16; i++) s = fmaf(a2[i], fc3w[i], s);
        out[g] = s;
    }
}

// ---------------- host side ----------------

template <int MI, int MO>
static void run_layer(const float* ea, const int* ei,
                      const float* w1, const float* b1,
                      const float* w2, const float* b2,
                      const float* root, const float* bias,
                      int insel, int outsel) {
    hid_kernel<<<EE, 128>>>(ea, w1, b1);
    dim3 pg(MO, (NN + 63) / 64);
    p2_kernel<MI, MO><<<pg, 256>>>(w2, insel);
    rb_kernel<MI, MO><<<(NN * MO + 255) / 256, 256>>>(b2, root, bias, insel);
    edge2_kernel<MO><<<EE / (256 / MO), 256>>>(ei);
    elu_kernel<MO><<<(NN * MO + 255) / 256, 256>>>(outsel);
}

extern "C" void kernel_launch(void* const* d_in, const int* in_sizes, int n_in,
                              void* d_out, int out_size) {
    const float* x  = (const float*)d_in[0];
    const int*   ei = (const int*)d_in[1];
    const float* ea = (const float*)d_in[2];
    const int*   batch = (const int*)d_in[3];

    const float* c1w1 = (const float*)d_in[4];
    const float* c1b1 = (const float*)d_in[5];
    const float* c1w2 = (const float*)d_in[6];
    const float* c1b2 = (const float*)d_in[7];
    const float* c1root = (const float*)d_in[8];
    const float* c1bias = (const float*)d_in[9];

    const float* c2w1 = (const float*)d_in[10];
    const float* c2b1 = (const float*)d_in[11];
    const float* c2w2 = (const float*)d_in[12];
    const float* c2b2 = (const float*)d_in[13];
    const float* c2root = (const float*)d_in[14];
    const float* c2bias = (const float*)d_in[15];

    const float* c3w1 = (const float*)d_in[16];
    const float* c3b1 = (const float*)d_in[17];
    const float* c3w2 = (const float*)d_in[18];
    const float* c3b2 = (const float*)d_in[19];
    const float* c3root = (const float*)d_in[20];
    const float* c3bias = (const float*)d_in[21];

    const float* fc1w = (const float*)d_in[22];
    const float* fc1b = (const float*)d_in[23];
    const float* fc2w = (const float*)d_in[24];
    const float* fc2b = (const float*)d_in[25];
    const float* fc3w = (const float*)d_in[26];
    const float* fc3b = (const float*)d_in[27];

    init_h0_kernel<<<(NN * CSD + 255) / 256, 256>>>(x);

    run_layer<5, 32>(ea, ei, c1w1, c1b1, c1w2, c1b2, c1root, c1bias, 0, 1);
    run_layer<32, 64>(ea, ei, c2w1, c2b1, c2w2, c2b2, c2root, c2bias, 1, 0);
    run_layer<64, 64>(ea, ei, c3w1, c3b1, c3w2, c3b2, c3root, c3bias, 0, 1);

    zero_pool_kernel<<<(GG * FCIN + 255) / 256, 256>>>();
    pool_scatter_kernel<<<(NN * FCIN + 255) / 256, 256>>>(x, batch, 1);
    mlp_kernel<<<GG, 32>>>(fc1w, fc1b, fc2w, fc2b, fc3w, fc3b, (float*)d_out);
}